// round 14
// baseline (speedup 1.0000x reference)
#include <cuda_runtime.h>
#include <cuda_fp16.h>
#include <cstdint>

// RoutingLinear == GEMM + bias: O[t][v] = sum_d X[t][d]*W[v][d] + b[v]
// X[2048,4096] fp32, W[32000,4096] fp32, b[32000], O[2048,32000] fp32.
//
// R14: eliminate the W fp16 pre-pass (was 1024MB of DRAM traffic: 512 R +
// 256 W + 256 R). The GEMM reads W directly as fp32 and converts in-loop:
// within a wave all 16 mtiles of an ntile are co-resident, so fp32 W is
// L2-served (28MB live << 126MB L2) and W DRAM traffic = 512MB read-once.
// B-tile staging becomes LDG.128(fp32, one iter ahead) -> CVT -> STS.128,
// riding the same barrier chain as the R12 skeleton. A-side staging, warp
// tiling, MMA order are byte-identical to R12 (1836.8us best).
//
// GEMM: BM=128, BN=64, BK=32, 4-stage ring, 3 CTAs/SM, warp tile 32x32,
// single leading sync per k-iter.

#define NTHR 256
#define BM 128
#define BN 64
#define BK 32
#define STAGES 4
#define TS 40                         // smem row stride in halfs (32 + 8 pad)
#define TILE_A_BYTES (BM * TS * 2)    // 10240
#define TILE_B_BYTES (BN * TS * 2)    // 5120
#define STAGE_BYTES (TILE_A_BYTES + TILE_B_BYTES)  // 15360
#define SMEM_NEED (STAGES * STAGE_BYTES)           // 61440 -> 3 CTAs/SM

#define T_MAX 2048
#define D_MAX 4096

// ---------------- scratch (static device memory; no allocs allowed) ----------
__device__ __half g_Xh[(size_t)T_MAX * D_MAX];

// ---------------- helpers -----------------------------------------------------
__device__ __forceinline__ uint32_t smem_u32_of(const void* p) {
    uint32_t a;
    asm("{ .reg .u64 t; cvta.to.shared.u64 t, %1; cvt.u32.u64 %0, t; }"
        : "=r"(a) : "l"(p));
    return a;
}
__device__ __forceinline__ void cp_async16(uint32_t dst, const void* src) {
    asm volatile("cp.async.cg.shared.global [%0], [%1], 16;"
                 :: "r"(dst), "l"(src) : "memory");
}
__device__ __forceinline__ void ldmatrix_x4(uint32_t& r0, uint32_t& r1,
                                            uint32_t& r2, uint32_t& r3,
                                            uint32_t addr) {
    asm volatile("ldmatrix.sync.aligned.m8n8.x4.shared.b16 {%0,%1,%2,%3}, [%4];"
                 : "=r"(r0), "=r"(r1), "=r"(r2), "=r"(r3) : "r"(addr));
}
__device__ __forceinline__ void mma_f16(float* d, const uint32_t* a,
                                        const uint32_t* b) {
    asm volatile(
        "mma.sync.aligned.m16n8k16.row.col.f32.f16.f16.f32 "
        "{%0,%1,%2,%3}, {%4,%5,%6,%7}, {%8,%9}, {%0,%1,%2,%3};"
        : "+f"(d[0]), "+f"(d[1]), "+f"(d[2]), "+f"(d[3])
        : "r"(a[0]), "r"(a[1]), "r"(a[2]), "r"(a[3]), "r"(b[0]), "r"(b[1]));
}
__device__ __forceinline__ uint4 cvt8_f32_to_h8(float4 b0, float4 b1) {
    __half2 h0 = __floats2half2_rn(b0.x, b0.y);
    __half2 h1 = __floats2half2_rn(b0.z, b0.w);
    __half2 h2 = __floats2half2_rn(b1.x, b1.y);
    __half2 h3 = __floats2half2_rn(b1.z, b1.w);
    uint4 r;
    r.x = *(uint32_t*)&h0; r.y = *(uint32_t*)&h1;
    r.z = *(uint32_t*)&h2; r.w = *(uint32_t*)&h3;
    return r;
}

// ---------------- X convert kernel (MLP=4; grid*NTHR*4 == n4 exactly) ----------
__global__ void conv_X_kernel(const float4* __restrict__ src, long n4) {
    uint2* __restrict__ dst = reinterpret_cast<uint2*>(g_Xh);
    const long base = (long)blockIdx.x * (NTHR * 4) + threadIdx.x;
    float4 v[4];
#pragma unroll
    for (int k = 0; k < 4; ++k) v[k] = src[base + k * NTHR];
#pragma unroll
    for (int k = 0; k < 4; ++k) {
        __half2 h0 = __floats2half2_rn(v[k].x, v[k].y);
        __half2 h1 = __floats2half2_rn(v[k].z, v[k].w);
        dst[base + k * NTHR] = make_uint2(*(uint32_t*)&h0, *(uint32_t*)&h1);
    }
}

// ---------------- GEMM ----------------------------------------------------------
__global__ __launch_bounds__(NTHR, 3)
void gemm_f16_kernel(const float* __restrict__ Wf,   // fp32 W [V][K]
                     const float* __restrict__ Bv,
                     float* __restrict__ O,
                     int T, int V, int K) {
    extern __shared__ char smem[];
    const uint32_t sbase = smem_u32_of(smem);

    const int tid  = threadIdx.x;
    const int wid  = tid >> 5;
    const int lane = tid & 31;
    const int wm   = wid & 3;      // 4 m-groups of 32 rows
    const int wn   = wid >> 2;     // 2 n-groups of 32 cols
    const int mtile = blockIdx.x;
    const int ntile = blockIdx.y;

    // ---- A staging (cp.async, as R12): 128 rows x 4 segs, 2 loads/thread
    const int srow = tid >> 2;           // 0..63
    const int seg  = tid & 3;            // 16B segment within 32-half row
    const __half* gA0 = g_Xh + (size_t)(mtile * BM + srow) * K + seg * 8;
    const __half* gA1 = gA0 + (size_t)64 * K;
    const uint32_t sdstA0 = (uint32_t)(srow * (TS * 2) + seg * 16);
    const uint32_t sdstA1 = sdstA0 + 64 * (TS * 2);

    // ---- B staging (LDG fp32 -> CVT -> STS): 64 rows x 4 segs, 8 fp32/thread
    const float* gBf = Wf + (size_t)(ntile * BN + srow) * K + seg * 8;
    const uint32_t sdstB = sdstA0;       // same row/seg mapping inside B tile

    // ---- ldmatrix per-lane base offsets (bytes, relative to tile bases) ----
    const int a_row = wm * 32 + (lane & 7) + ((lane >> 3) & 1) * 8;
    const uint32_t a_off = (uint32_t)(a_row * (TS * 2) + (lane >> 4) * 16);
    const int b_row = wn * 32 + (lane & 7) + ((lane >> 4) & 1) * 8;
    const uint32_t b_off = (uint32_t)(b_row * (TS * 2) + ((lane >> 3) & 1) * 16);

    float acc[2][4][4];
#pragma unroll
    for (int i = 0; i < 2; ++i)
#pragma unroll
        for (int j = 0; j < 4; ++j)
#pragma unroll
            for (int c = 0; c < 4; ++c) acc[i][j][c] = 0.f;

    const int KT = K / BK;  // 128

    auto issue_stage_A = [&](int t) {
        const uint32_t st = sbase + (uint32_t)(t % STAGES) * STAGE_BYTES;
        const size_t kb = (size_t)t * BK;
        cp_async16(st + sdstA0, gA0 + kb);
        cp_async16(st + sdstA1, gA1 + kb);
        asm volatile("cp.async.commit_group;" ::: "memory");
    };

    // prologue: A stages 0..2 async; B stages 0..2 synchronous LDG+CVT+STS
    issue_stage_A(0);
    issue_stage_A(1);
    issue_stage_A(2);
#pragma unroll
    for (int s = 0; s < 3; ++s) {
        const size_t kb = (size_t)s * BK;
        float4 b0 = *reinterpret_cast<const float4*>(gBf + kb);
        float4 b1 = *reinterpret_cast<const float4*>(gBf + kb + 4);
        *reinterpret_cast<uint4*>(smem + s * STAGE_BYTES + TILE_A_BYTES + sdstB)
            = cvt8_f32_to_h8(b0, b1);
    }
    // prime regs for B stage 3 (consumed by STS at t=1)
    float4 bb0, bb1;
    {
        const size_t kb = (size_t)3 * BK;
        bb0 = *reinterpret_cast<const float4*>(gBf + kb);
        bb1 = *reinterpret_cast<const float4*>(gBf + kb + 4);
    }

    for (int t = 0; t < KT; ++t) {
        asm volatile("cp.async.wait_group 2;" ::: "memory");
        __syncthreads();   // A stage t visible; all threads past iter t-1
                           // reads -> slot (t-1)%4 reusable for A and B writes
        if (t + 3 < KT) issue_stage_A(t + 3);

        // B: store stage t+2 (regs LDG'd at iter t-1), then prefetch t+3.
        // slot (t+2)%4 == (t-2)%4: its readers finished at iter t-2, two
        // barriers ago; visibility to iter-(t+2) readers via barriers t+1,t+2.
        if (t >= 1 && t + 2 < KT) {
            *reinterpret_cast<uint4*>(
                smem + ((t + 2) % STAGES) * STAGE_BYTES + TILE_A_BYTES + sdstB)
                = cvt8_f32_to_h8(bb0, bb1);
        }
        if (t + 3 < KT) {
            const size_t kb = (size_t)(t + 3) * BK;
            bb0 = *reinterpret_cast<const float4*>(gBf + kb);
            bb1 = *reinterpret_cast<const float4*>(gBf + kb + 4);
        }

        const uint32_t st = sbase + (uint32_t)(t % STAGES) * STAGE_BYTES;
        const uint32_t aAdr = st + a_off;
        const uint32_t bAdr = st + TILE_A_BYTES + b_off;

#pragma unroll
        for (int ks = 0; ks < 2; ++ks) {
            const uint32_t koff = (uint32_t)(ks * 32);  // 16 halfs = 32B
            uint32_t af[2][4];
            ldmatrix_x4(af[0][0], af[0][1], af[0][2], af[0][3], aAdr + koff);
            ldmatrix_x4(af[1][0], af[1][1], af[1][2], af[1][3],
                        aAdr + koff + 16 * (TS * 2));
            uint32_t bf[2][4];
#pragma unroll
            for (int jp = 0; jp < 2; ++jp)
                ldmatrix_x4(bf[jp][0], bf[jp][1], bf[jp][2], bf[jp][3],
                            bAdr + koff + (uint32_t)(jp * 16 * (TS * 2)));
#pragma unroll
            for (int im = 0; im < 2; ++im)
#pragma unroll
                for (int jn = 0; jn < 4; ++jn) {
                    uint32_t breg[2] = { bf[jn >> 1][(jn & 1) * 2],
                                         bf[jn >> 1][(jn & 1) * 2 + 1] };
                    mma_f16(acc[im][jn], af[im], breg);
                }
        }
        // single sync per iter: next leading barrier protects slot reuse.
    }

    // ---- epilogue: bias + store ----
    const int r_base = mtile * BM + wm * 32 + (lane >> 2);
    const int c_base = ntile * BN + wn * 32 + (lane & 3) * 2;
#pragma unroll
    for (int im = 0; im < 2; ++im) {
#pragma unroll
        for (int jn = 0; jn < 4; ++jn) {
            const int col = c_base + jn * 8;
            const float2 bv = *reinterpret_cast<const float2*>(Bv + col);
            const int r0 = r_base + im * 16;
            float2 o0 = make_float2(acc[im][jn][0] + bv.x, acc[im][jn][1] + bv.y);
            float2 o1 = make_float2(acc[im][jn][2] + bv.x, acc[im][jn][3] + bv.y);
            *reinterpret_cast<float2*>(O + (size_t)r0 * V + col)       = o0;
            *reinterpret_cast<float2*>(O + (size_t)(r0 + 8) * V + col) = o1;
        }
    }
}

// ---------------- launch --------------------------------------------------------
extern "C" void kernel_launch(void* const* d_in, const int* in_sizes, int n_in,
                              void* d_out, int out_size) {
    const float* X  = (const float*)d_in[0];  // [T, D]
    const float* W  = (const float*)d_in[1];  // [V, D]
    const float* Bv = (const float*)d_in[2];  // [V]
    float* O = (float*)d_out;                 // [T, V]

    const int V = in_sizes[2];
    const int D = in_sizes[1] / V;
    const int T = in_sizes[0] / D;

    const long nx4 = (long)T * D / 4;
    conv_X_kernel<<<(unsigned)(nx4 / (NTHR * 4)), NTHR>>>((const float4*)X, nx4);

    cudaFuncSetAttribute(gemm_f16_kernel,
                         cudaFuncAttributeMaxDynamicSharedMemorySize, SMEM_NEED);
    dim3 grid(T / BM, V / BN);  // (16, 500); x fastest -> fp32 W L2 reuse
    gemm_f16_kernel<<<grid, NTHR, SMEM_NEED>>>(W, Bv, O, T, V, D);
}

// round 15
// speedup vs baseline: 1.1376x; 1.1376x over previous
#include <cuda_runtime.h>
#include <cuda_fp16.h>
#include <cstdint>

// RoutingLinear == GEMM + bias: O[t][v] = sum_d X[t][d]*W[v][d] + b[v]
// X[2048,4096] fp32, W[32000,4096] fp32, b[32000], O[2048,32000] fp32.
//
// FINAL (R12 artifact, re-submitted after R13/R14 probes regressed for
// understood reasons):
//  - fp16-in / fp32-accumulate legacy HMMA (mma.sync m16n8k16) GEMM at the
//    measured L1tex<->HMMA equilibrium (~1.72ms; tensor-pipe paced, LDSM
//    wavefront-fed). CTA tile 128x64, BK=32, 4-stage cp.async ring,
//    3 CTAs/SM, warp tile 32x32, single leading __syncthreads per k-iter.
//  - MLP=4 convert pre-pass at the DRAM floor (conv_W ~106us @ 88% DRAM).
//  - R13 (5-stage ring) lost 3-CTA residency: 3x76.8KB > usable smem/SM.
//  - R14 (in-loop W conversion) saturated L1 (84.4%) and starved LDSM.
//  - tcgen05 is unavailable: harness compiles via compute_103 virtual arch,
//    which rejects all tcgen05/TMEM PTX.

#define NTHR 256
#define BM 128
#define BN 64
#define BK 32
#define STAGES 4
#define TS 40                         // smem row stride in halfs (32 + 8 pad)
#define TILE_A_BYTES (BM * TS * 2)    // 10240
#define TILE_B_BYTES (BN * TS * 2)    // 5120
#define STAGE_BYTES (TILE_A_BYTES + TILE_B_BYTES)  // 15360
#define SMEM_NEED (STAGES * STAGE_BYTES)           // 61440 -> 3 CTAs/SM

#define T_MAX 2048
#define D_MAX 4096
#define V_MAX 32000

// ---------------- scratch (static device memory; no allocs allowed) ----------
__device__ __half g_Xh[(size_t)T_MAX * D_MAX];
__device__ __half g_Wh[(size_t)V_MAX * D_MAX];

// ---------------- helpers -----------------------------------------------------
__device__ __forceinline__ uint32_t smem_u32_of(const void* p) {
    uint32_t a;
    asm("{ .reg .u64 t; cvta.to.shared.u64 t, %1; cvt.u32.u64 %0, t; }"
        : "=r"(a) : "l"(p));
    return a;
}
__device__ __forceinline__ void cp_async16(uint32_t dst, const void* src) {
    asm volatile("cp.async.cg.shared.global [%0], [%1], 16;"
                 :: "r"(dst), "l"(src) : "memory");
}
__device__ __forceinline__ void ldmatrix_x4(uint32_t& r0, uint32_t& r1,
                                            uint32_t& r2, uint32_t& r3,
                                            uint32_t addr) {
    asm volatile("ldmatrix.sync.aligned.m8n8.x4.shared.b16 {%0,%1,%2,%3}, [%4];"
                 : "=r"(r0), "=r"(r1), "=r"(r2), "=r"(r3) : "r"(addr));
}
__device__ __forceinline__ void mma_f16(float* d, const uint32_t* a,
                                        const uint32_t* b) {
    asm volatile(
        "mma.sync.aligned.m16n8k16.row.col.f32.f16.f16.f32 "
        "{%0,%1,%2,%3}, {%4,%5,%6,%7}, {%8,%9}, {%0,%1,%2,%3};"
        : "+f"(d[0]), "+f"(d[1]), "+f"(d[2]), "+f"(d[3])
        : "r"(a[0]), "r"(a[1]), "r"(a[2]), "r"(a[3]), "r"(b[0]), "r"(b[1]));
}

// ---------------- convert kernels (MLP=4; grid*NTHR*4 == n4 exactly) -----------
__global__ void conv_X_kernel(const float4* __restrict__ src, long n4) {
    uint2* __restrict__ dst = reinterpret_cast<uint2*>(g_Xh);
    const long base = (long)blockIdx.x * (NTHR * 4) + threadIdx.x;
    float4 v[4];
#pragma unroll
    for (int k = 0; k < 4; ++k) v[k] = src[base + k * NTHR];
#pragma unroll
    for (int k = 0; k < 4; ++k) {
        __half2 h0 = __floats2half2_rn(v[k].x, v[k].y);
        __half2 h1 = __floats2half2_rn(v[k].z, v[k].w);
        dst[base + k * NTHR] = make_uint2(*(uint32_t*)&h0, *(uint32_t*)&h1);
    }
}
__global__ void conv_W_kernel(const float4* __restrict__ src, long n4) {
    uint2* __restrict__ dst = reinterpret_cast<uint2*>(g_Wh);
    const long base = (long)blockIdx.x * (NTHR * 4) + threadIdx.x;
    float4 v[4];
#pragma unroll
    for (int k = 0; k < 4; ++k) v[k] = src[base + k * NTHR];
#pragma unroll
    for (int k = 0; k < 4; ++k) {
        __half2 h0 = __floats2half2_rn(v[k].x, v[k].y);
        __half2 h1 = __floats2half2_rn(v[k].z, v[k].w);
        dst[base + k * NTHR] = make_uint2(*(uint32_t*)&h0, *(uint32_t*)&h1);
    }
}

// ---------------- GEMM ----------------------------------------------------------
__global__ __launch_bounds__(NTHR, 3)
void gemm_f16_kernel(const float* __restrict__ Bv,
                     float* __restrict__ O,
                     int T, int V, int K) {
    extern __shared__ char smem[];
    const uint32_t sbase = smem_u32_of(smem);

    const int tid  = threadIdx.x;
    const int wid  = tid >> 5;
    const int lane = tid & 31;
    const int wm   = wid & 3;      // 4 m-groups of 32 rows
    const int wn   = wid >> 2;     // 2 n-groups of 32 cols
    const int mtile = blockIdx.x;
    const int ntile = blockIdx.y;

    // ---- staging: A = 128 rows x 4 segs (2/thread), B = 64 rows x 4 segs (1/thread)
    const int srowA = tid >> 2;          // 0..63 (A rows: srowA and srowA+64)
    const int seg   = tid & 3;           // 16B segment within 32-half row
    const __half* gA0 = g_Xh + (size_t)(mtile * BM + srowA) * K + seg * 8;
    const __half* gA1 = gA0 + (size_t)64 * K;
    const __half* gB  = g_Wh + (size_t)(ntile * BN + srowA) * K + seg * 8;
    const uint32_t sdstA0 = (uint32_t)(srowA * (TS * 2) + seg * 16);
    const uint32_t sdstA1 = sdstA0 + 64 * (TS * 2);
    const uint32_t sdstB  = sdstA0;      // same row/seg mapping inside B tile

    // ---- ldmatrix per-lane base offsets (bytes, relative to tile bases) ----
    const int a_row = wm * 32 + (lane & 7) + ((lane >> 3) & 1) * 8;
    const uint32_t a_off = (uint32_t)(a_row * (TS * 2) + (lane >> 4) * 16);
    const int b_row = wn * 32 + (lane & 7) + ((lane >> 4) & 1) * 8;
    const uint32_t b_off = (uint32_t)(b_row * (TS * 2) + ((lane >> 3) & 1) * 16);

    float acc[2][4][4];
#pragma unroll
    for (int i = 0; i < 2; ++i)
#pragma unroll
        for (int j = 0; j < 4; ++j)
#pragma unroll
            for (int c = 0; c < 4; ++c) acc[i][j][c] = 0.f;

    const int KT = K / BK;  // 128

    auto issue_stage = [&](int t) {
        const uint32_t st = sbase + (uint32_t)(t % STAGES) * STAGE_BYTES;
        const size_t kb = (size_t)t * BK;
        cp_async16(st + sdstA0,               gA0 + kb);
        cp_async16(st + sdstA1,               gA1 + kb);
        cp_async16(st + TILE_A_BYTES + sdstB, gB + kb);
        asm volatile("cp.async.commit_group;" ::: "memory");
    };

    issue_stage(0);
    issue_stage(1);
    issue_stage(2);

    for (int t = 0; t < KT; ++t) {
        asm volatile("cp.async.wait_group 2;" ::: "memory");
        __syncthreads();   // stage t visible; all threads past iter t-1 reads
                           // -> safe to overwrite slot (t+3)%4 == (t-1)%4
        if (t + 3 < KT) issue_stage(t + 3);

        const uint32_t st = sbase + (uint32_t)(t % STAGES) * STAGE_BYTES;
        const uint32_t aAdr = st + a_off;
        const uint32_t bAdr = st + TILE_A_BYTES + b_off;

#pragma unroll
        for (int ks = 0; ks < 2; ++ks) {
            const uint32_t koff = (uint32_t)(ks * 32);  // 16 halfs = 32B
            uint32_t af[2][4];
            ldmatrix_x4(af[0][0], af[0][1], af[0][2], af[0][3], aAdr + koff);
            ldmatrix_x4(af[1][0], af[1][1], af[1][2], af[1][3],
                        aAdr + koff + 16 * (TS * 2));
            uint32_t bf[2][4];
#pragma unroll
            for (int jp = 0; jp < 2; ++jp)
                ldmatrix_x4(bf[jp][0], bf[jp][1], bf[jp][2], bf[jp][3],
                            bAdr + koff + (uint32_t)(jp * 16 * (TS * 2)));
#pragma unroll
            for (int im = 0; im < 2; ++im)
#pragma unroll
                for (int jn = 0; jn < 4; ++jn) {
                    uint32_t breg[2] = { bf[jn >> 1][(jn & 1) * 2],
                                         bf[jn >> 1][(jn & 1) * 2 + 1] };
                    mma_f16(acc[im][jn], af[im], breg);
                }
        }
        // single sync per iter: next leading barrier protects slot reuse.
    }

    // ---- epilogue: bias + store ----
    const int r_base = mtile * BM + wm * 32 + (lane >> 2);
    const int c_base = ntile * BN + wn * 32 + (lane & 3) * 2;
#pragma unroll
    for (int im = 0; im < 2; ++im) {
#pragma unroll
        for (int jn = 0; jn < 4; ++jn) {
            const int col = c_base + jn * 8;
            const float2 bv = *reinterpret_cast<const float2*>(Bv + col);
            const int r0 = r_base + im * 16;
            float2 o0 = make_float2(acc[im][jn][0] + bv.x, acc[im][jn][1] + bv.y);
            float2 o1 = make_float2(acc[im][jn][2] + bv.x, acc[im][jn][3] + bv.y);
            *reinterpret_cast<float2*>(O + (size_t)r0 * V + col)       = o0;
            *reinterpret_cast<float2*>(O + (size_t)(r0 + 8) * V + col) = o1;
        }
    }
}

// ---------------- launch --------------------------------------------------------
extern "C" void kernel_launch(void* const* d_in, const int* in_sizes, int n_in,
                              void* d_out, int out_size) {
    const float* X  = (const float*)d_in[0];  // [T, D]
    const float* W  = (const float*)d_in[1];  // [V, D]
    const float* Bv = (const float*)d_in[2];  // [V]
    float* O = (float*)d_out;                 // [T, V]

    const int V = in_sizes[2];
    const int D = in_sizes[1] / V;
    const int T = in_sizes[0] / D;

    const long nx4 = (long)T * D / 4;
    const long nw4 = (long)V * D / 4;
    conv_W_kernel<<<(unsigned)(nw4 / (NTHR * 4)), NTHR>>>((const float4*)W, nw4);
    conv_X_kernel<<<(unsigned)(nx4 / (NTHR * 4)), NTHR>>>((const float4*)X, nx4);

    cudaFuncSetAttribute(gemm_f16_kernel,
                         cudaFuncAttributeMaxDynamicSharedMemorySize, SMEM_NEED);
    dim3 grid(T / BM, V / BN);  // (16, 500); x fastest -> W tile reuse in L2
    gemm_f16_kernel<<<grid, NTHR, SMEM_NEED>>>(Bv, O, T, V, D);
}

// round 16
// speedup vs baseline: 1.2216x; 1.0738x over previous
#include <cuda_runtime.h>
#include <cuda_fp16.h>
#include <cstdint>

// RoutingLinear == GEMM + bias: O[t][v] = sum_d X[t][d]*W[v][d] + b[v]
// X[2048,4096] fp32, W[32000,4096] fp32, b[32000], O[2048,32000] fp32.
//
// R16: same validated skeleton (fp16-in/fp32-acc HMMA, BM=128 BN=64 BK=32,
// 4-stage cp.async ring, 3 CTAs/SM, single leading sync), but warp tile
// 32x64 with 4 warps/CTA (128 threads):
//   - per-SMSP HMMA pressure unchanged (3 warps x 32 = 96 HMMA/iter),
//   - LDSM wavefronts per MAC -25% (larger B-fragment reuse),
//   - half the barrier participants and ~20% fewer issues per MAC.
// Tests whether the ~570 MAC/cyc/SM plateau has a non-tensor component.

#define NTHR 128
#define BM 128
#define BN 64
#define BK 32
#define STAGES 4
#define TS 40                         // smem row stride in halfs (32 + 8 pad)
#define TILE_A_BYTES (BM * TS * 2)    // 10240
#define TILE_B_BYTES (BN * TS * 2)    // 5120
#define STAGE_BYTES (TILE_A_BYTES + TILE_B_BYTES)  // 15360
#define SMEM_NEED (STAGES * STAGE_BYTES)           // 61440 -> 3 CTAs/SM

#define CNVT 256                      // conv kernels keep 256 threads
#define T_MAX 2048
#define D_MAX 4096
#define V_MAX 32000

// ---------------- scratch (static device memory; no allocs allowed) ----------
__device__ __half g_Xh[(size_t)T_MAX * D_MAX];
__device__ __half g_Wh[(size_t)V_MAX * D_MAX];

// ---------------- helpers -----------------------------------------------------
__device__ __forceinline__ uint32_t smem_u32_of(const void* p) {
    uint32_t a;
    asm("{ .reg .u64 t; cvta.to.shared.u64 t, %1; cvt.u32.u64 %0, t; }"
        : "=r"(a) : "l"(p));
    return a;
}
__device__ __forceinline__ void cp_async16(uint32_t dst, const void* src) {
    asm volatile("cp.async.cg.shared.global [%0], [%1], 16;"
                 :: "r"(dst), "l"(src) : "memory");
}
__device__ __forceinline__ void ldmatrix_x4(uint32_t& r0, uint32_t& r1,
                                            uint32_t& r2, uint32_t& r3,
                                            uint32_t addr) {
    asm volatile("ldmatrix.sync.aligned.m8n8.x4.shared.b16 {%0,%1,%2,%3}, [%4];"
                 : "=r"(r0), "=r"(r1), "=r"(r2), "=r"(r3) : "r"(addr));
}
__device__ __forceinline__ void mma_f16(float* d, const uint32_t* a,
                                        const uint32_t* b) {
    asm volatile(
        "mma.sync.aligned.m16n8k16.row.col.f32.f16.f16.f32 "
        "{%0,%1,%2,%3}, {%4,%5,%6,%7}, {%8,%9}, {%0,%1,%2,%3};"
        : "+f"(d[0]), "+f"(d[1]), "+f"(d[2]), "+f"(d[3])
        : "r"(a[0]), "r"(a[1]), "r"(a[2]), "r"(a[3]), "r"(b[0]), "r"(b[1]));
}

// ---------------- convert kernels (MLP=4; grid*CNVT*4 == n4 exactly) -----------
__global__ void conv_X_kernel(const float4* __restrict__ src, long n4) {
    uint2* __restrict__ dst = reinterpret_cast<uint2*>(g_Xh);
    const long base = (long)blockIdx.x * (CNVT * 4) + threadIdx.x;
    float4 v[4];
#pragma unroll
    for (int k = 0; k < 4; ++k) v[k] = src[base + k * CNVT];
#pragma unroll
    for (int k = 0; k < 4; ++k) {
        __half2 h0 = __floats2half2_rn(v[k].x, v[k].y);
        __half2 h1 = __floats2half2_rn(v[k].z, v[k].w);
        dst[base + k * CNVT] = make_uint2(*(uint32_t*)&h0, *(uint32_t*)&h1);
    }
}
__global__ void conv_W_kernel(const float4* __restrict__ src, long n4) {
    uint2* __restrict__ dst = reinterpret_cast<uint2*>(g_Wh);
    const long base = (long)blockIdx.x * (CNVT * 4) + threadIdx.x;
    float4 v[4];
#pragma unroll
    for (int k = 0; k < 4; ++k) v[k] = src[base + k * CNVT];
#pragma unroll
    for (int k = 0; k < 4; ++k) {
        __half2 h0 = __floats2half2_rn(v[k].x, v[k].y);
        __half2 h1 = __floats2half2_rn(v[k].z, v[k].w);
        dst[base + k * CNVT] = make_uint2(*(uint32_t*)&h0, *(uint32_t*)&h1);
    }
}

// ---------------- GEMM ----------------------------------------------------------
__global__ __launch_bounds__(NTHR, 3)
void gemm_f16_kernel(const float* __restrict__ Bv,
                     float* __restrict__ O,
                     int T, int V, int K) {
    extern __shared__ char smem[];
    const uint32_t sbase = smem_u32_of(smem);

    const int tid  = threadIdx.x;
    const int wid  = tid >> 5;      // 0..3 -> m-group of 32 rows; all warps span n=64
    const int lane = tid & 31;
    const int mtile = blockIdx.x;
    const int ntile = blockIdx.y;

    // ---- staging (128 thr): A = 128 rows x 4 segs (4/thread), B = 64 x 4 (2/thread)
    const int srow = tid >> 2;           // 0..31
    const int seg  = tid & 3;            // 16B segment within 32-half row
    const __half* gA = g_Xh + (size_t)(mtile * BM + srow) * K + seg * 8;
    const __half* gB = g_Wh + (size_t)(ntile * BN + srow) * K + seg * 8;
    const uint32_t sdstA = (uint32_t)(srow * (TS * 2) + seg * 16);
    const uint32_t sdstB = sdstA;

    // ---- ldmatrix per-lane base offsets (bytes, relative to tile bases) ----
    const int a_row = wid * 32 + (lane & 7) + ((lane >> 3) & 1) * 8;
    const uint32_t a_off = (uint32_t)(a_row * (TS * 2) + (lane >> 4) * 16);
    const int b_row = (lane & 7) + ((lane >> 4) & 1) * 8;
    const uint32_t b_off = (uint32_t)(b_row * (TS * 2) + ((lane >> 3) & 1) * 16);

    float acc[2][8][4];
#pragma unroll
    for (int i = 0; i < 2; ++i)
#pragma unroll
        for (int j = 0; j < 8; ++j)
#pragma unroll
            for (int c = 0; c < 4; ++c) acc[i][j][c] = 0.f;

    const int KT = K / BK;  // 128

    auto issue_stage = [&](int t) {
        const uint32_t st = sbase + (uint32_t)(t % STAGES) * STAGE_BYTES;
        const size_t kb = (size_t)t * BK;
#pragma unroll
        for (int i = 0; i < 4; ++i)   // A rows srow, srow+32, srow+64, srow+96
            cp_async16(st + sdstA + (uint32_t)(i * 32 * (TS * 2)),
                       gA + kb + (size_t)(i * 32) * K);
#pragma unroll
        for (int i = 0; i < 2; ++i)   // B rows srow, srow+32
            cp_async16(st + TILE_A_BYTES + sdstB + (uint32_t)(i * 32 * (TS * 2)),
                       gB + kb + (size_t)(i * 32) * K);
        asm volatile("cp.async.commit_group;" ::: "memory");
    };

    issue_stage(0);
    issue_stage(1);
    issue_stage(2);

    for (int t = 0; t < KT; ++t) {
        asm volatile("cp.async.wait_group 2;" ::: "memory");
        __syncthreads();   // stage t visible; all threads past iter t-1 reads
                           // -> safe to overwrite slot (t+3)%4 == (t-1)%4
        if (t + 3 < KT) issue_stage(t + 3);

        const uint32_t st = sbase + (uint32_t)(t % STAGES) * STAGE_BYTES;
        const uint32_t aAdr = st + a_off;
        const uint32_t bAdr = st + TILE_A_BYTES + b_off;

#pragma unroll
        for (int ks = 0; ks < 2; ++ks) {
            const uint32_t koff = (uint32_t)(ks * 32);  // 16 halfs = 32B
            uint32_t af[2][4];
            ldmatrix_x4(af[0][0], af[0][1], af[0][2], af[0][3], aAdr + koff);
            ldmatrix_x4(af[1][0], af[1][1], af[1][2], af[1][3],
                        aAdr + koff + 16 * (TS * 2));
            uint32_t bf[4][4];   // 4 n16-pairs -> 8 n8 tiles (all 64 cols)
#pragma unroll
            for (int jp = 0; jp < 4; ++jp)
                ldmatrix_x4(bf[jp][0], bf[jp][1], bf[jp][2], bf[jp][3],
                            bAdr + koff + (uint32_t)(jp * 16 * (TS * 2)));
#pragma unroll
            for (int im = 0; im < 2; ++im)
#pragma unroll
                for (int jn = 0; jn < 8; ++jn) {
                    uint32_t breg[2] = { bf[jn >> 1][(jn & 1) * 2],
                                         bf[jn >> 1][(jn & 1) * 2 + 1] };
                    mma_f16(acc[im][jn], af[im], breg);
                }
        }
        // single sync per iter: next leading barrier protects slot reuse.
    }

    // ---- epilogue: bias + store (warp covers rows wid*32..+31, all 64 cols) ----
    const int r_base = mtile * BM + wid * 32 + (lane >> 2);
    const int c_base = ntile * BN + (lane & 3) * 2;
#pragma unroll
    for (int im = 0; im < 2; ++im) {
#pragma unroll
        for (int jn = 0; jn < 8; ++jn) {
            const int col = c_base + jn * 8;
            const float2 bv = *reinterpret_cast<const float2*>(Bv + col);
            const int r0 = r_base + im * 16;
            float2 o0 = make_float2(acc[im][jn][0] + bv.x, acc[im][jn][1] + bv.y);
            float2 o1 = make_float2(acc[im][jn][2] + bv.x, acc[im][jn][3] + bv.y);
            *reinterpret_cast<float2*>(O + (size_t)r0 * V + col)       = o0;
            *reinterpret_cast<float2*>(O + (size_t)(r0 + 8) * V + col) = o1;
        }
    }
}

// ---------------- launch --------------------------------------------------------
extern "C" void kernel_launch(void* const* d_in, const int* in_sizes, int n_in,
                              void* d_out, int out_size) {
    const float* X  = (const float*)d_in[0];  // [T, D]
    const float* W  = (const float*)d_in[1];  // [V, D]
    const float* Bv = (const float*)d_in[2];  // [V]
    float* O = (float*)d_out;                 // [T, V]

    const int V = in_sizes[2];
    const int D = in_sizes[1] / V;
    const int T = in_sizes[0] / D;

    const long nx4 = (long)T * D / 4;
    const long nw4 = (long)V * D / 4;
    conv_W_kernel<<<(unsigned)(nw4 / (CNVT * 4)), CNVT>>>((const float4*)W, nw4);
    conv_X_kernel<<<(unsigned)(nx4 / (CNVT * 4)), CNVT>>>((const float4*)X, nx4);

    cudaFuncSetAttribute(gemm_f16_kernel,
                         cudaFuncAttributeMaxDynamicSharedMemorySize, SMEM_NEED);
    dim3 grid(T / BM, V / BN);  // (16, 500); x fastest -> W tile reuse in L2
    gemm_f16_kernel<<<grid, NTHR, SMEM_NEED>>>(Bv, O, T, V, D);
}